// round 2
// baseline (speedup 1.0000x reference)
#include <cuda_runtime.h>
#include <math.h>

// SinusoidalOscillator: out[b,n] = sin( exclusive_cumsum_f32( f0_b * (1 + env[b,:]*amt_b) )[n] )
// The cumsum must bit-match jax.lax.associative_scan's recursion (jnp.cumsum lowering
// on CPU/GPU backends), padded with a leading zero (length 65537):
//   L_{k+1}[i] = L_k[2i] + L_k[2i+1]
//   S_k[0] = L_k[0];  S_k[2i+1] = S_{k+1}[i];  S_k[2i+2] = S_{k+1}[i] + L_k[2i+2]
// All f32 ops via __fadd_rn/__fmul_rn (no FMA contraction) to match XLA rounding.

#define NSAMP   65536
#define CHUNK   8192
#define NCHUNK  (NSAMP / CHUNK)
#define BS      1024

// smem: lev[32767] (L2..L16 / S2..S16), fes[CHUNK+4], s1s[CHUNK/2+8]
#define LEV_PAD   32768
#define FES_PAD   (CHUNK + 8)
#define S1_PAD    (CHUNK/2 + 8)
#define SMEM_FLOATS (LEV_PAD + FES_PAD + S1_PAD)
#define SMEM_BYTES  (SMEM_FLOATS * 4)

// off(k) = 32768 - (NSAMP >> (k-1)) : start of level-k array (k = 2..16)
__device__ __forceinline__ int lev_off(int k) { return 32768 - (NSAMP >> (k - 1)); }

__global__ __launch_bounds__(BS, 1)
void osc_kernel(const float* __restrict__ freq,
                const float* __restrict__ env,
                const float* __restrict__ moda,
                float* __restrict__ out)
{
    extern __shared__ float sm[];
    float* lev = sm;                    // 32767 used
    float* fes = sm + LEV_PAD;          // staged x[base-2 .. base+CHUNK-1]
    float* s1s = sm + LEV_PAD + FES_PAD;

    const int row = blockIdx.x;
    const int tid = threadIdx.x;

    // de-normalize controls, exactly as the reference does it (mul-then-add, no fma)
    const float f0hz = __fadd_rn(20.0f, __fmul_rn(1980.0f, freq[row]));
    const float f0   = __fdiv_rn(__fmul_rn(f0hz, 6.28318530717958647692f), 48000.0f);
    const float am   = __fadd_rn(-1.0f, __fmul_rn(3.0f, moda[row]));

    const float* e = env + (size_t)row * NSAMP;
    float*       o = out + (size_t)row * NSAMP;

    // ---------------- up phase: build L2 (16384 entries) ----------------
    for (int c = 0; c < NCHUNK; ++c) {
        const int base = c * CHUNK;
        // stage x[j] for j in [base-2, base+CHUNK): x[0]=0, x[j]=f0 + (e[j-1]*am)*f0
        for (int t = tid; t < CHUNK + 2; t += BS) {
            int j = base - 2 + t;
            float v = 0.0f;
            if (j >= 1) v = __fadd_rn(f0, __fmul_rn(__fmul_rn(e[j - 1], am), f0));
            fes[t] = v;
        }
        __syncthreads();
        // L2[i] = (x[4i]+x[4i+1]) + (x[4i+2]+x[4i+3])   (== L1[2i]+L1[2i+1])
        for (int q = tid; q < CHUNK / 4; q += BS) {
            float a = fes[4*q + 2], b = fes[4*q + 3];
            float g = fes[4*q + 4], d = fes[4*q + 5];
            lev[c * (CHUNK / 4) + q] = __fadd_rn(__fadd_rn(a, b), __fadd_rn(g, d));
        }
        __syncthreads();
    }

    // ---------------- build L3..L16 ----------------
    for (int k = 2; k <= 15; ++k) {
        const int offk  = lev_off(k);
        const int offk1 = lev_off(k + 1);
        const int half  = NSAMP >> (k + 1);
        for (int i = tid; i < half; i += BS)
            lev[offk1 + i] = __fadd_rn(lev[offk + 2*i], lev[offk + 2*i + 1]);
        __syncthreads();
    }

    // ---------------- scan S15..S2 in place (S16 == L16) ----------------
    for (int k = 15; k >= 2; --k) {
        const int offk  = lev_off(k);
        const int offk1 = lev_off(k + 1);
        const int half  = NSAMP >> (k + 1);
        for (int i = tid; i < half; i += BS) {
            float sp = lev[offk1 + i];          // S_{k+1}[i]
            // in place over L_k: each i owns positions 2i+1 and 2i+2
            if (i < half - 1) {
                float l = lev[offk + 2*i + 2];
                lev[offk + 2*i + 1] = sp;
                lev[offk + 2*i + 2] = __fadd_rn(sp, l);
            } else {
                lev[offk + 2*i + 1] = sp;
            }
        }
        __syncthreads();
    }
    // now lev[0..16383] holds S2.

    // ---------------- down phase: reconstruct S1, S0, emit sin ----------------
    for (int c = 0; c < NCHUNK; ++c) {
        const int base = c * CHUNK;
        __syncthreads();   // protect fes/s1s reuse from previous chunk's readers
        for (int t = tid; t < CHUNK + 2; t += BS) {
            int j = base - 2 + t;
            float v = 0.0f;
            if (j >= 1) v = __fadd_rn(f0, __fmul_rn(__fmul_rn(e[j - 1], am), f0));
            fes[t] = v;
        }
        __syncthreads();

        // S1[m] for m in [mb, mb + CHUNK/2], mb = c*CHUNK/2 - 1 (one-element halo)
        const int mb = c * (CHUNK / 2) - 1;
        for (int idx = tid; idx <= CHUNK / 2; idx += BS) {
            int m = mb + idx;
            float v;
            if (m < 0)        v = 0.0f;                 // unused (c==0, idx==0)
            else if (m == 0)  v = fes[3];               // S1[0] = 0 + x[1] = x[1]
            else if (m & 1)   v = lev[(m - 1) >> 1];    // S1[2i+1] = S2[i]
            else {
                // S1[2i+2] = S2[i] + L1[2i+2];  L1[m] = x[2m] + x[2m+1]
                float l1 = __fadd_rn(fes[2*m - base + 2], fes[2*m + 1 - base + 2]);
                v = __fadd_rn(lev[(m - 2) >> 1], l1);
            }
            s1s[idx] = v;
        }
        __syncthreads();

        // S0[0]=0; S0[2m+1]=S1[m]; S0[2m+2]=S1[m]+x[2m+2]
        for (int t = tid; t < CHUNK; t += BS) {
            int n = base + t;
            float ph;
            if (n == 0)      ph = 0.0f;
            else if (n & 1)  ph = s1s[((n - 1) >> 1) - mb];
            else             ph = __fadd_rn(s1s[((n - 2) >> 1) - mb], fes[t + 2]);
            o[n] = sinf(ph);
        }
    }
}

extern "C" void kernel_launch(void* const* d_in, const int* in_sizes, int n_in,
                              void* d_out, int out_size)
{
    // Identify inputs robustly: mod_env is the largest; the two size-B float
    // inputs are, in metadata order, freq then mod_amount.
    int im = 0;
    for (int i = 1; i < n_in; ++i)
        if (in_sizes[i] > in_sizes[im]) im = i;
    const int B = in_sizes[im] / NSAMP;

    const float* freqp = nullptr;
    const float* amtp  = nullptr;
    for (int i = 0; i < n_in; ++i) {
        if (i == im) continue;
        if (in_sizes[i] == B) {
            if (!freqp) freqp = (const float*)d_in[i];
            else if (!amtp) amtp = (const float*)d_in[i];
        }
    }
    const float* envp = (const float*)d_in[im];

    cudaFuncSetAttribute(osc_kernel, cudaFuncAttributeMaxDynamicSharedMemorySize,
                         SMEM_BYTES);
    osc_kernel<<<B, BS, SMEM_BYTES>>>(freqp, envp, amtp, (float*)d_out);
}